// round 14
// baseline (speedup 1.0000x reference)
#include <cuda_runtime.h>
#include <cuda_fp16.h>
#include <cstdint>

#define CC   3
#define OO   8
#define HH   128
#define WW   128
#define HO   124
#define WO   124
#define P25  25

#define XT_W  68                  // 64-wide tile + 4 halo (even)
#define XT_H  18                  // 14-row tile + 4 halo

typedef unsigned long long ull;

// Two adjacent output columns from a shared 6-tap-per-row ring.
// w[slot*6+t] = (x, -x) half2, slot = xrow % 5; kp[p] = (-K_hit, +K_miss).
// Col A uses taps t=0..4, col B taps t=1..5 (same kp index per u,v).
template<int J>
__device__ __forceinline__ float2 row_compute2(const __half2* __restrict__ w,
                                               const __half2* __restrict__ kp)
{
    __half2 ca[5], cb[5];
#pragma unroll
    for (int u = 0; u < 5; ++u) {
        const int s = ((J + u) % 5) * 6;
        __half2 a = __hadd2(w[s],     kp[u * 5]);
        __half2 b = __hadd2(w[s + 1], kp[u * 5]);
#pragma unroll
        for (int v = 1; v < 5; ++v) {
            a = __hmin2(a, __hadd2(w[s + v],     kp[u * 5 + v]));
            b = __hmin2(b, __hadd2(w[s + v + 1], kp[u * 5 + v]));
        }
        ca[u] = a; cb[u] = b;
    }
    const __half2 ra = __hmin2(__hmin2(__hmin2(ca[0], ca[1]),
                                       __hmin2(ca[2], ca[3])), ca[4]);
    const __half2 rb = __hmin2(__hmin2(__hmin2(cb[0], cb[1]),
                                       __hmin2(cb[2], cb[3])), cb[4]);
    return make_float2(__low2float(ra) + __high2float(ra),
                       __low2float(rb) + __high2float(rb));
}

// Load x row (rbase+J+4) into ring slot (J+4)%5 via 3 LDS.64 (6 taps),
// compute both columns of output row rbase+J, store one float2.
#define ROW_STEP(J)                                                              \
    do {                                                                         \
        const ull* nr = (const ull*)(sxr + ((J) + 4) * XT_W);                    \
        const int sl = (((J) + 4) % 5) * 6;                                      \
        *(ull*)&w[sl]     = nr[0];                                               \
        *(ull*)&w[sl + 2] = nr[1];                                               \
        *(ull*)&w[sl + 4] = nr[2];                                               \
        op[(J) * (WO / 2)] = row_compute2<(J)>(w, kp);                           \
    } while (0)

__global__ __launch_bounds__(256, 3)
void mnn_kernel(const float* __restrict__ x,
                const float* __restrict__ kh_g,
                const float* __restrict__ km_g,
                float* __restrict__ out)
{
    __shared__ __half2 sxh[XT_H * XT_W];   // (x, -x) tile: 18 x 68
    __shared__ __half2 wsm[OO * P25];      // (-kh, +km) for all 8 o, this c

    const int tx  = threadIdx.x;           // 0..31 -> columns 2tx, 2tx+1
    const int o   = threadIdx.y;           // 0..7  output channel
    const int tid = o * 32 + tx;

    // x-tiles at {0, 60} (even), 64 wide -> covers [0,123]; y-tiles of 14
    // rows, last at 110. Overlap cells rewritten with identical values.
    const int wo0 = blockIdx.x * 60;
    const int ho0 = (blockIdx.y == 8) ? 110 : blockIdx.y * 14;
    const int bc  = blockIdx.z;             // b*CC + c
    const int b   = bc / CC;
    const int c   = bc % CC;

    // ---- cooperative weight staging: 1 LDG pair per thread (tid < 200) ----
    if (tid < OO * P25) {
        const int oo = tid / P25;
        const int p  = tid % P25;
        const float kh = __ldg(kh_g + (oo * CC + c) * P25 + p);
        const float km = __ldg(km_g + (oo * CC + c) * P25 + p);
        wsm[tid] = __halves2half2(__float2half_rn(-kh), __float2half_rn(km));
    }

    // ---- x tile staged via float2 (aligned: wo0, cc even), as (x,-x) ----
    const float* __restrict__ xb = x + (size_t)bc * HH * WW;
    for (int i = tid; i < (XT_H * XT_W) / 2; i += 256) {     // 612 pairs
        const int e   = 2 * i;
        const int rr  = e / XT_W;
        const int cc2 = e % XT_W;                            // even
        const float2 v2 = *(const float2*)(xb + (ho0 + rr) * WW + wo0 + cc2);
        const __half h0 = __float2half_rn(v2.x);
        const __half h1 = __float2half_rn(v2.y);
        sxh[e]     = __halves2half2(h0, __hneg(h0));
        sxh[e + 1] = __halves2half2(h1, __hneg(h1));
    }
    __syncthreads();

    // ---- per-thread weights from smem (warp-uniform broadcast LDS) ----
    __half2 kp[P25];
    {
        const __half2* __restrict__ wp = &wsm[o * P25];
#pragma unroll
        for (int p = 0; p < P25; ++p) kp[p] = wp[p];
    }

    // ---- ring prologue: x rows 0..3 into slots 0..3 (3 LDS.64 each) ----
    __half2 w[30];                           // 5 rows x 6 taps
#pragma unroll
    for (int i = 0; i < 4; ++i) {
        const ull* rp = (const ull*)(sxh + i * XT_W + 2 * tx);
        *(ull*)&w[i * 6]     = rp[0];
        *(ull*)&w[i * 6 + 2] = rp[1];
        *(ull*)&w[i * 6 + 4] = rp[2];
    }

    float2* __restrict__ op = (float2*)
        (out + ((size_t)(b * OO * CC + o * CC + c) * HO + ho0) * WO
             + wo0 + 2 * tx);

    const __half2* sxr = sxh + 2 * tx;       // advances 5 rows per chunk

    // ---- 2 chunks x 5 rows + 4 tail = 14 output rows ----
#pragma unroll 1
    for (int rc = 0; rc < 2; ++rc) {
        ROW_STEP(0);
        ROW_STEP(1);
        ROW_STEP(2);
        ROW_STEP(3);
        ROW_STEP(4);
        sxr += 5 * XT_W;
        op  += 5 * (WO / 2);
    }
    ROW_STEP(0);   // row 10
    ROW_STEP(1);   // row 11
    ROW_STEP(2);   // row 12
    ROW_STEP(3);   // row 13
}

extern "C" void kernel_launch(void* const* d_in, const int* in_sizes, int n_in,
                              void* d_out, int out_size)
{
    const float* x     = (const float*)d_in[0];
    const float* K_hit = (const float*)d_in[1];
    const float* K_mis = (const float*)d_in[2];
    float* out = (float*)d_out;

    dim3 grid(2, 9, OO * CC);     // 432 blocks, cap 3/SM -> 97% single wave
    dim3 block(32, 8);
    mnn_kernel<<<grid, block>>>(x, K_hit, K_mis, out);
}

// round 15
// speedup vs baseline: 1.0025x; 1.0025x over previous
#include <cuda_runtime.h>
#include <cuda_fp16.h>
#include <cstdint>

#define CC   3
#define OO   8
#define HH   128
#define WW   128
#define HO   124
#define WO   124
#define P25  25

#define ROWSPAN 21                // 6 overlapping row-tiles: 0,21,42,63,84,103
#define XT_W  36                  // 32 + 4 halo
#define XT_H  25                  // 21 + 4 halo

// One output row from the 5-slot ring (slot = xrow % 5), phase J = row % 5.
// w[p] = (x, -x) half2; kp[p] = (-K_hit, +K_miss) half2.
// min over both halves of (w + kp) yields (hit, -miss).
template<int J>
__device__ __forceinline__ float row_compute(const __half2* __restrict__ w,
                                             const __half2* __restrict__ kp)
{
    __half2 cu[5];
#pragma unroll
    for (int u = 0; u < 5; ++u) {
        const int s = ((J + u) % 5) * 5;
        __half2 acc = __hadd2(w[s], kp[u * 5]);
#pragma unroll
        for (int v = 1; v < 5; ++v)
            acc = __hmin2(acc, __hadd2(w[s + v], kp[u * 5 + v]));
        cu[u] = acc;
    }
    const __half2 r = __hmin2(__hmin2(__hmin2(cu[0], cu[1]),
                                      __hmin2(cu[2], cu[3])), cu[4]);
    return __low2float(r) + __high2float(r);   // hit - miss
}

// Row R (0-based within tile): load x row R+4 into ring slot (R+4)%5 at a
// STATIC smem offset, compute, store at STATIC output offset. No pointers
// mutate -> no loop-carried address chains, no branches.
#define ROW_STEP(R)                                                              \
    do {                                                                         \
        const __half2* nr = sxr + ((R) + 4) * XT_W;                              \
        _Pragma("unroll")                                                        \
        for (int v = 0; v < 5; ++v)                                              \
            w[(((R) + 4) % 5) * 5 + v] = nr[v];                                  \
        op[(R) * WO] = row_compute<(R) % 5>(w, kp);                              \
    } while (0)

__global__ __launch_bounds__(256, 4)
void mnn_kernel(const float* __restrict__ x,
                const float* __restrict__ kh_g,
                const float* __restrict__ km_g,
                float* __restrict__ out)
{
    __shared__ __half2 sxh[XT_H * XT_W];   // (x, -x) tile: 25 x 36
    __shared__ __half2 wsm[OO * P25];      // (-kh, +km) for all 8 o, this c

    const int tx  = threadIdx.x;           // 0..31 column
    const int o   = threadIdx.y;           // 0..7  output channel
    const int tid = o * 32 + tx;

    // Overlapping tiles both axes -> all store lanes in-range; overlap cells
    // rewritten with identical values (deterministic). Even column origins
    // keep the float2 staging loads 8-byte aligned.
    static const int WO0[4] = {0, 30, 62, 92};
    const int wo0 = WO0[blockIdx.x];
    const int ho0 = (blockIdx.y == 5) ? 103 : blockIdx.y * ROWSPAN;
    const int bc  = blockIdx.z;             // b*CC + c
    const int b   = bc / CC;
    const int c   = bc % CC;

    // ---- cooperative weight staging: 1 LDG pair per thread (tid < 200) ----
    if (tid < OO * P25) {
        const int oo = tid / P25;
        const int p  = tid % P25;
        const float kh = __ldg(kh_g + (oo * CC + c) * P25 + p);
        const float km = __ldg(km_g + (oo * CC + c) * P25 + p);
        wsm[tid] = __halves2half2(__float2half_rn(-kh), __float2half_rn(km));
    }

    // ---- x tile staged via float2 (2 LDG.64/thread), packed (x, -x) ----
    const float* __restrict__ xb = x + (size_t)bc * HH * WW;
    for (int i = tid; i < (XT_H * XT_W) / 2; i += 256) {     // 450 pairs
        const int e   = 2 * i;
        const int rr  = e / XT_W;
        const int cc2 = e % XT_W;                            // even
        const float2 v2 = *(const float2*)(xb + (ho0 + rr) * WW + wo0 + cc2);
        const __half h0 = __float2half_rn(v2.x);
        const __half h1 = __float2half_rn(v2.y);
        sxh[e]     = __halves2half2(h0, __hneg(h0));
        sxh[e + 1] = __halves2half2(h1, __hneg(h1));
    }
    __syncthreads();

    // ---- per-thread weights from smem (warp-uniform broadcast LDS) ----
    __half2 kp[P25];
    {
        const __half2* __restrict__ wp = &wsm[o * P25];
#pragma unroll
        for (int p = 0; p < P25; ++p) kp[p] = wp[p];
    }

    // ---- ring prologue: x rows 0..3 into slots 0..3 ----
    __half2 w[P25];
#pragma unroll
    for (int i = 0; i < 4; ++i)
#pragma unroll
        for (int v = 0; v < 5; ++v)
            w[i * 5 + v] = sxh[i * XT_W + tx + v];

    float* __restrict__ op =
        out + ((size_t)(b * OO * CC + o * CC + c) * HO + ho0) * WO + wo0 + tx;

    const __half2* __restrict__ sxr = sxh + tx;

    // ---- 21 output rows, fully unrolled, all offsets static ----
    ROW_STEP(0);  ROW_STEP(1);  ROW_STEP(2);  ROW_STEP(3);  ROW_STEP(4);
    ROW_STEP(5);  ROW_STEP(6);  ROW_STEP(7);  ROW_STEP(8);  ROW_STEP(9);
    ROW_STEP(10); ROW_STEP(11); ROW_STEP(12); ROW_STEP(13); ROW_STEP(14);
    ROW_STEP(15); ROW_STEP(16); ROW_STEP(17); ROW_STEP(18); ROW_STEP(19);
    ROW_STEP(20);
}

extern "C" void kernel_launch(void* const* d_in, const int* in_sizes, int n_in,
                              void* d_out, int out_size)
{
    const float* x     = (const float*)d_in[0];
    const float* K_hit = (const float*)d_in[1];
    const float* K_mis = (const float*)d_in[2];
    float* out = (float*)d_out;

    dim3 grid(4, 6, OO * CC);     // 576 blocks, cap 4/SM -> balanced single wave
    dim3 block(32, 8);
    mnn_kernel<<<grid, block>>>(x, K_hit, K_mis, out);
}